// round 2
// baseline (speedup 1.0000x reference)
#include <cuda_runtime.h>

#define L 8
#define B 128
#define NL 32
#define NP 256
#define N_LIG (B*NL)
#define N_PROT (B*NP)
#define E_PL_G 1024
#define E_LL_G 256
#define F 128
#define H 256
#define OUT 2

// Scratch (device globals; no allocation allowed in kernel_launch)
__device__ float g_pooled_pl[L * B * F];   // per-(layer,graph) pooled, scaled aggregated inputs (PL relation)
__device__ float g_pooled_ll[L * B * F];   // same, LL relation
__device__ float g_weff_pl[L * F * OUT];   // W_pl[l] @ W_fc[l*H:(l+1)*H]
__device__ float g_weff_ll[L * F * OUT];
__device__ float g_beff[OUT];              // b_fc + sum_l (b_pl[l]+b_ll[l]) @ W_fc[l]

struct SmemAgg {
    alignas(16) float partial[8 * F];  // per-warp pooled partials (16B-aligned: float4 stores)
    unsigned short pack[E_PL_G];       // (dst_local<<8) | src_local
    unsigned char  sorted_src[E_PL_G]; // src_local sorted by dst bucket
    int   cnt_src[NP];
    float rs_src[NP];
    int   cnt_dst[NL];
    int   off[NL + 1];
    int   cursor[NL];
    float rs_dst[NL];
};

// One relation for one (layer, graph): degree-normalize src features, aggregate
// per dst node (counting-sorted, register accumulators), scale by rsqrt(deg_dst),
// mean-pool over the 32 ligand dst nodes, write 128-float pooled vector.
__device__ __forceinline__ void relation_pool(
    const float* __restrict__ feat,    // this layer's feature base (global node rows)
    const int* __restrict__ src, const int* __restrict__ dst, // this graph's edge block
    int n_edges, int n_src, int src_base, int dst_base,
    float* __restrict__ pooled, SmemAgg& s)
{
    const int tid = threadIdx.x;

    // zero counters
    for (int i = tid; i < n_src; i += 256) s.cnt_src[i] = 0;
    if (tid < NL) s.cnt_dst[tid] = 0;
    __syncthreads();

    // load edges, localize indices, count degrees
    for (int e = tid; e < n_edges; e += 256) {
        int sl = src[e] - src_base;
        int dl = dst[e] - dst_base;
        s.pack[e] = (unsigned short)((dl << 8) | sl);
        atomicAdd(&s.cnt_src[sl], 1);
        atomicAdd(&s.cnt_dst[dl], 1);
    }
    __syncthreads();

    // rsqrt of clipped degrees
    for (int i = tid; i < n_src; i += 256) {
        int c = s.cnt_src[i];
        s.rs_src[i] = rsqrtf((float)(c > 0 ? c : 1));
    }
    // prefix-sum the 32 dst counts (warp 0)
    if (tid < NL) {
        int c = s.cnt_dst[tid];
        s.rs_dst[tid] = rsqrtf((float)(c > 0 ? c : 1));
        int x = c;
        #pragma unroll
        for (int o = 1; o < 32; o <<= 1) {
            int y = __shfl_up_sync(0xffffffffu, x, o);
            if (tid >= o) x += y;
        }
        s.off[tid + 1] = x;
        s.cursor[tid] = x - c;
        if (tid == 0) s.off[0] = 0;
    }
    __syncthreads();

    // counting-sort scatter: group edges by dst
    for (int e = tid; e < n_edges; e += 256) {
        unsigned short p = s.pack[e];
        int dl = p >> 8;
        int pos = atomicAdd(&s.cursor[dl], 1);
        s.sorted_src[pos] = (unsigned char)(p & 255);
    }
    __syncthreads();

    // each warp owns dst nodes {w, w+8, w+16, w+24}; accumulate in registers.
    // lane covers floats [4*lane, 4*lane+4) of the 128-wide row.
    const int warp = tid >> 5, lane = tid & 31;
    float4 part = make_float4(0.f, 0.f, 0.f, 0.f);
    for (int d = warp; d < NL; d += 8) {
        float4 acc = make_float4(0.f, 0.f, 0.f, 0.f);
        const int beg = s.off[d], end = s.off[d + 1];
        for (int i = beg; i < end; i++) {
            int sl = s.sorted_src[i];
            const float4* row = (const float4*)(feat + (size_t)(src_base + sl) * F);
            float4 v = __ldg(&row[lane]);
            float sc = s.rs_src[sl];
            acc.x += v.x * sc; acc.y += v.y * sc;
            acc.z += v.z * sc; acc.w += v.w * sc;
        }
        float rd = s.rs_dst[d];
        part.x += acc.x * rd; part.y += acc.y * rd;
        part.z += acc.z * rd; part.w += acc.w * rd;
    }
    ((float4*)(s.partial + warp * F))[lane] = part;
    __syncthreads();

    // reduce 8 warp partials -> pooled (with the 1/NL graph-mean folded in)
    if (tid < F) {
        float sum = 0.f;
        #pragma unroll
        for (int w = 0; w < 8; w++) sum += s.partial[w * F + tid];
        pooled[tid] = sum * (1.0f / (float)NL);
    }
    __syncthreads(); // protect smem reuse by next relation
}

__global__ __launch_bounds__(256) void agg_kernel(
    const float* __restrict__ feat_lig, const float* __restrict__ feat_prot,
    const int* __restrict__ src_pl, const int* __restrict__ dst_pl,
    const int* __restrict__ src_ll, const int* __restrict__ dst_ll)
{
    __shared__ SmemAgg s;
    const int l = blockIdx.x / B;
    const int b = blockIdx.x % B;

    const float* fp = feat_prot + (size_t)l * N_PROT * F;
    const float* fl = feat_lig  + (size_t)l * N_LIG  * F;

    const size_t pl_off = (size_t)l * B * E_PL_G + (size_t)b * E_PL_G;
    const size_t ll_off = (size_t)l * B * E_LL_G + (size_t)b * E_LL_G;

    relation_pool(fp, src_pl + pl_off, dst_pl + pl_off,
                  E_PL_G, NP, b * NP, b * NL,
                  g_pooled_pl + ((size_t)l * B + b) * F, s);

    relation_pool(fl, src_ll + ll_off, dst_ll + ll_off,
                  E_LL_G, NL, b * NL, b * NL,
                  g_pooled_ll + ((size_t)l * B + b) * F, s);
}

// Weff[rel][l][f][o] = sum_h W_rel[l,f,h] * W_fc[l*H+h, o];  beff[o] = b_fc[o] + sum_{l,h}(b_pl+b_ll)*W_fc
__global__ __launch_bounds__(256) void weff_kernel(
    const float* __restrict__ W_pl, const float* __restrict__ W_ll,
    const float* __restrict__ b_pl, const float* __restrict__ b_ll,
    const float* __restrict__ W_fc, const float* __restrict__ b_fc)
{
    const int l   = blockIdx.x;
    const int f   = threadIdx.x & 127;
    const int rel = threadIdx.x >> 7;

    const float* W    = rel ? W_ll : W_pl;
    float*       Weff = rel ? g_weff_ll : g_weff_pl;

    const float* wrow = W + ((size_t)l * F + f) * H;
    const float* fc   = W_fc + (size_t)l * H * OUT;

    float a0 = 0.f, a1 = 0.f;
    #pragma unroll 8
    for (int h = 0; h < H; h++) {
        float w = wrow[h];
        a0 += w * fc[h * OUT + 0];
        a1 += w * fc[h * OUT + 1];
    }
    Weff[((size_t)l * F + f) * OUT + 0] = a0;
    Weff[((size_t)l * F + f) * OUT + 1] = a1;

    if (blockIdx.x == 0 && threadIdx.x < OUT) {
        const int o = threadIdx.x;
        float a = b_fc[o];
        for (int j = 0; j < L * H; j++)
            a += (b_pl[j] + b_ll[j]) * W_fc[j * OUT + o];
        g_beff[o] = a;
    }
}

__global__ __launch_bounds__(128) void final_kernel(float* __restrict__ out)
{
    const int b = blockIdx.x;
    const int f = threadIdx.x;  // 0..127

    float a0 = 0.f, a1 = 0.f;
    #pragma unroll
    for (int l = 0; l < L; l++) {
        float pp = g_pooled_pl[((size_t)l * B + b) * F + f];
        float pl = g_pooled_ll[((size_t)l * B + b) * F + f];
        const int wi = (l * F + f) * OUT;
        a0 += pp * g_weff_pl[wi + 0] + pl * g_weff_ll[wi + 0];
        a1 += pp * g_weff_pl[wi + 1] + pl * g_weff_ll[wi + 1];
    }

    __shared__ float red[2][128];
    red[0][f] = a0; red[1][f] = a1;
    __syncthreads();
    #pragma unroll
    for (int st = 64; st > 0; st >>= 1) {
        if (f < st) { red[0][f] += red[0][f + st]; red[1][f] += red[1][f + st]; }
        __syncthreads();
    }
    if (f < OUT) {
        float v = red[f][0] + g_beff[f];
        out[b * OUT + f] = 1.0f / (1.0f + expf(-v));
    }
}

extern "C" void kernel_launch(void* const* d_in, const int* in_sizes, int n_in,
                              void* d_out, int out_size)
{
    const float* feat_lig  = (const float*)d_in[0];
    const float* feat_prot = (const float*)d_in[1];
    const int*   src_pl    = (const int*)  d_in[2];
    const int*   dst_pl    = (const int*)  d_in[3];
    const int*   src_ll    = (const int*)  d_in[4];
    const int*   dst_ll    = (const int*)  d_in[5];
    const float* W_pl      = (const float*)d_in[6];
    const float* b_pl      = (const float*)d_in[7];
    const float* W_ll      = (const float*)d_in[8];
    const float* b_ll      = (const float*)d_in[9];
    const float* W_fc      = (const float*)d_in[10];
    const float* b_fc      = (const float*)d_in[11];
    float* out = (float*)d_out;

    weff_kernel<<<L, 256>>>(W_pl, W_ll, b_pl, b_ll, W_fc, b_fc);
    agg_kernel<<<L * B, 256>>>(feat_lig, feat_prot, src_pl, dst_pl, src_ll, dst_ll);
    final_kernel<<<B, 128>>>(out);
}

// round 3
// speedup vs baseline: 4.5950x; 4.5950x over previous
#include <cuda_runtime.h>

#define L 8
#define B 128
#define NL 32
#define NP 256
#define N_LIG (B*NL)
#define N_PROT (B*NP)
#define E_PL_G 1024
#define E_LL_G 256
#define F 128
#define H 256
#define OUT 2

// Scratch (device globals; no allocation allowed in kernel_launch)
__device__ float g_pooled_pl[L * B * F];
__device__ float g_pooled_ll[L * B * F];
__device__ float g_weff_pl[L * F * OUT];   // W_pl[l] @ W_fc[l*H:(l+1)*H]
__device__ float g_weff_ll[L * F * OUT];
__device__ float g_beff[OUT];

struct SmemAgg {
    alignas(16) float partial[8 * F];   // per-warp pooled partials
    unsigned short pack[E_PL_G];        // (dst_local<<8) | src_local
    int   cnt_src[NP];
    float coeff[NP];
    int   cnt_dst[NL];
    float rs_dst[NL];
};

// pooled[f] = sum_s coeff[s] * feat[src_base+s][f],
// coeff[s]  = rs_src[s] * (1/NL) * sum_{e: src=s} rs_dst[dst_e]
__device__ __forceinline__ void relation_pool(
    const float* __restrict__ feat,
    const int* __restrict__ src, const int* __restrict__ dst,
    int n_edges, int n_src, int src_base, int dst_base,
    float* __restrict__ pooled, SmemAgg& s)
{
    const int tid = threadIdx.x;

    // zero counters
    for (int i = tid; i < n_src; i += 256) s.cnt_src[i] = 0;
    if (tid < NL) s.cnt_dst[tid] = 0;
    __syncthreads();

    // load edges, localize, count degrees
    for (int e = tid; e < n_edges; e += 256) {
        int sl = src[e] - src_base;
        int dl = dst[e] - dst_base;
        s.pack[e] = (unsigned short)((dl << 8) | sl);
        atomicAdd(&s.cnt_src[sl], 1);
        atomicAdd(&s.cnt_dst[dl], 1);
    }
    __syncthreads();

    if (tid < NL) {
        int c = s.cnt_dst[tid];
        s.rs_dst[tid] = rsqrtf((float)(c > 0 ? c : 1));
    }
    for (int i = tid; i < n_src; i += 256) s.coeff[i] = 0.f;
    __syncthreads();

    // accumulate per-src coefficient
    for (int e = tid; e < n_edges; e += 256) {
        unsigned short p = s.pack[e];
        atomicAdd(&s.coeff[p & 255], s.rs_dst[p >> 8]);
    }
    __syncthreads();

    // fold rs_src and the 1/NL graph-mean
    for (int i = tid; i < n_src; i += 256) {
        int c = s.cnt_src[i];
        s.coeff[i] *= rsqrtf((float)(c > 0 ? c : 1)) * (1.0f / (float)NL);
    }
    __syncthreads();

    // dense, streaming weighted row-sum: warp w owns rows [w*per, (w+1)*per);
    // lane covers floats [4*lane, 4*lane+4) (full 512B row per warp, coalesced)
    const int warp = tid >> 5, lane = tid & 31;
    const int per = n_src >> 3;
    float4 part = make_float4(0.f, 0.f, 0.f, 0.f);
    for (int r = warp * per; r < (warp + 1) * per; r++) {
        float c = s.coeff[r];
        if (c != 0.f) {
            const float4* row = (const float4*)(feat + (size_t)(src_base + r) * F);
            float4 v = __ldg(&row[lane]);
            part.x += c * v.x; part.y += c * v.y;
            part.z += c * v.z; part.w += c * v.w;
        }
    }
    ((float4*)(s.partial + warp * F))[lane] = part;
    __syncthreads();

    if (tid < F) {
        float sum = 0.f;
        #pragma unroll
        for (int w = 0; w < 8; w++) sum += s.partial[w * F + tid];
        pooled[tid] = sum;
    }
    __syncthreads(); // smem reused by next relation
}

__global__ __launch_bounds__(256) void agg_kernel(
    const float* __restrict__ feat_lig, const float* __restrict__ feat_prot,
    const int* __restrict__ src_pl, const int* __restrict__ dst_pl,
    const int* __restrict__ src_ll, const int* __restrict__ dst_ll)
{
    __shared__ SmemAgg s;
    const int l = blockIdx.x / B;
    const int b = blockIdx.x % B;

    const float* fp = feat_prot + (size_t)l * N_PROT * F;
    const float* fl = feat_lig  + (size_t)l * N_LIG  * F;

    const size_t pl_off = (size_t)l * B * E_PL_G + (size_t)b * E_PL_G;
    const size_t ll_off = (size_t)l * B * E_LL_G + (size_t)b * E_LL_G;

    relation_pool(fp, src_pl + pl_off, dst_pl + pl_off,
                  E_PL_G, NP, b * NP, b * NL,
                  g_pooled_pl + ((size_t)l * B + b) * F, s);

    relation_pool(fl, src_ll + ll_off, dst_ll + ll_off,
                  E_LL_G, NL, b * NL, b * NL,
                  g_pooled_ll + ((size_t)l * B + b) * F, s);
}

// blocks 0..255: one warp per (rel,l,f) row, warp-reduced dot over h.
// block 256: beff = b_fc + sum_j (b_pl+b_ll)[j] * W_fc[j,:], block reduction.
__global__ __launch_bounds__(256) void weff_kernel(
    const float* __restrict__ W_pl, const float* __restrict__ W_ll,
    const float* __restrict__ b_pl, const float* __restrict__ b_ll,
    const float* __restrict__ W_fc, const float* __restrict__ b_fc)
{
    const int tid  = threadIdx.x;
    const int warp = tid >> 5, lane = tid & 31;

    if (blockIdx.x < 256) {
        const int bid   = blockIdx.x;
        const int rel   = bid >> 7;          // 0: pl, 1: ll
        const int l     = (bid >> 4) & 7;
        const int f     = ((bid & 15) << 3) + warp;

        const float* W    = rel ? W_ll : W_pl;
        float*       Weff = rel ? g_weff_ll : g_weff_pl;

        const float* wrow = W + ((size_t)l * F + f) * H;
        const float* fc   = W_fc + (size_t)l * H * OUT;

        float a0 = 0.f, a1 = 0.f;
        #pragma unroll
        for (int h = lane; h < H; h += 32) {
            float w = wrow[h];
            a0 += w * fc[h * OUT + 0];
            a1 += w * fc[h * OUT + 1];
        }
        #pragma unroll
        for (int o = 16; o > 0; o >>= 1) {
            a0 += __shfl_xor_sync(0xffffffffu, a0, o);
            a1 += __shfl_xor_sync(0xffffffffu, a1, o);
        }
        if (lane == 0) {
            Weff[((size_t)l * F + f) * OUT + 0] = a0;
            Weff[((size_t)l * F + f) * OUT + 1] = a1;
        }
    } else {
        __shared__ float red0[256], red1[256];
        float a0 = 0.f, a1 = 0.f;
        for (int j = tid; j < L * H; j += 256) {
            float bb = b_pl[j] + b_ll[j];
            a0 += bb * W_fc[j * OUT + 0];
            a1 += bb * W_fc[j * OUT + 1];
        }
        red0[tid] = a0; red1[tid] = a1;
        __syncthreads();
        #pragma unroll
        for (int st = 128; st > 0; st >>= 1) {
            if (tid < st) { red0[tid] += red0[tid + st]; red1[tid] += red1[tid + st]; }
            __syncthreads();
        }
        if (tid == 0) {
            g_beff[0] = red0[0] + b_fc[0];
            g_beff[1] = red1[0] + b_fc[1];
        }
    }
}

__global__ __launch_bounds__(128) void final_kernel(float* __restrict__ out)
{
    const int b = blockIdx.x;
    const int f = threadIdx.x;  // 0..127

    float a0 = 0.f, a1 = 0.f;
    #pragma unroll
    for (int l = 0; l < L; l++) {
        float pp = g_pooled_pl[((size_t)l * B + b) * F + f];
        float pl = g_pooled_ll[((size_t)l * B + b) * F + f];
        const int wi = (l * F + f) * OUT;
        a0 += pp * g_weff_pl[wi + 0] + pl * g_weff_ll[wi + 0];
        a1 += pp * g_weff_pl[wi + 1] + pl * g_weff_ll[wi + 1];
    }

    __shared__ float red[2][128];
    red[0][f] = a0; red[1][f] = a1;
    __syncthreads();
    #pragma unroll
    for (int st = 64; st > 0; st >>= 1) {
        if (f < st) { red[0][f] += red[0][f + st]; red[1][f] += red[1][f + st]; }
        __syncthreads();
    }
    if (f < OUT) {
        float v = red[f][0] + g_beff[f];
        out[b * OUT + f] = 1.0f / (1.0f + expf(-v));
    }
}

extern "C" void kernel_launch(void* const* d_in, const int* in_sizes, int n_in,
                              void* d_out, int out_size)
{
    const float* feat_lig  = (const float*)d_in[0];
    const float* feat_prot = (const float*)d_in[1];
    const int*   src_pl    = (const int*)  d_in[2];
    const int*   dst_pl    = (const int*)  d_in[3];
    const int*   src_ll    = (const int*)  d_in[4];
    const int*   dst_ll    = (const int*)  d_in[5];
    const float* W_pl      = (const float*)d_in[6];
    const float* b_pl      = (const float*)d_in[7];
    const float* W_ll      = (const float*)d_in[8];
    const float* b_ll      = (const float*)d_in[9];
    const float* W_fc      = (const float*)d_in[10];
    const float* b_fc      = (const float*)d_in[11];
    float* out = (float*)d_out;

    weff_kernel<<<257, 256>>>(W_pl, W_ll, b_pl, b_ll, W_fc, b_fc);
    agg_kernel<<<L * B, 256>>>(feat_lig, feat_prot, src_pl, dst_pl, src_ll, dst_ll);
    final_kernel<<<B, 128>>>(out);
}

// round 4
// speedup vs baseline: 5.3498x; 1.1643x over previous
#include <cuda_runtime.h>

#define L 8
#define B 128
#define NL 32
#define NP 256
#define N_LIG (B*NL)
#define N_PROT (B*NP)
#define E_PL_G 1024
#define E_LL_G 256
#define F 128
#define H 256
#define OUT 2

#define WEFF_BLOCKS 257   // 256 weff-row blocks + 1 beff block
#define AGG_BLOCKS  (L*B)

// Scratch (device globals; no allocation allowed in kernel_launch)
__device__ float g_pooled_pl[L * B * F];
__device__ float g_pooled_ll[L * B * F];
__device__ float g_weff_pl[L * F * OUT];   // W_pl[l] @ W_fc[l*H:(l+1)*H]
__device__ float g_weff_ll[L * F * OUT];
__device__ float g_beff[OUT];

struct SmemAgg {
    alignas(16) float partial[8 * F];   // per-warp pooled partials
    unsigned short pack[E_PL_G];        // (dst_local<<8) | src_local
    int   cnt_src[NP];
    float coeff[NP];
    int   cnt_dst[NL];
    float rs_dst[NL];
};

// pooled[f] = sum_s coeff[s] * feat[src_base+s][f],
// coeff[s]  = rs_src[s] * (1/NL) * sum_{e: src=s} rs_dst[dst_e]
__device__ __forceinline__ void relation_pool(
    const float* __restrict__ feat,
    const int* __restrict__ src, const int* __restrict__ dst,
    int n_edges, int n_src, int src_base, int dst_base,
    float* __restrict__ pooled, SmemAgg& s)
{
    const int tid = threadIdx.x;

    // zero counters
    for (int i = tid; i < n_src; i += 256) s.cnt_src[i] = 0;
    if (tid < NL) s.cnt_dst[tid] = 0;
    __syncthreads();

    // load edges, localize, count degrees
    for (int e = tid; e < n_edges; e += 256) {
        int sl = src[e] - src_base;
        int dl = dst[e] - dst_base;
        s.pack[e] = (unsigned short)((dl << 8) | sl);
        atomicAdd(&s.cnt_src[sl], 1);
        atomicAdd(&s.cnt_dst[dl], 1);
    }
    __syncthreads();

    if (tid < NL) {
        int c = s.cnt_dst[tid];
        s.rs_dst[tid] = rsqrtf((float)(c > 0 ? c : 1));
    }
    for (int i = tid; i < n_src; i += 256) s.coeff[i] = 0.f;
    __syncthreads();

    // accumulate per-src coefficient
    for (int e = tid; e < n_edges; e += 256) {
        unsigned short p = s.pack[e];
        atomicAdd(&s.coeff[p & 255], s.rs_dst[p >> 8]);
    }
    __syncthreads();

    // fold rs_src and the 1/NL graph-mean
    for (int i = tid; i < n_src; i += 256) {
        int c = s.cnt_src[i];
        s.coeff[i] *= rsqrtf((float)(c > 0 ? c : 1)) * (1.0f / (float)NL);
    }
    __syncthreads();

    // dense, streaming weighted row-sum: warp w owns rows [w*per, (w+1)*per);
    // lane covers floats [4*lane, 4*lane+4); unrolled x4 for load batching (MLP)
    const int warp = tid >> 5, lane = tid & 31;
    const int per = n_src >> 3;
    const int r0 = warp * per;
    float4 part = make_float4(0.f, 0.f, 0.f, 0.f);
    #pragma unroll 4
    for (int r = r0; r < r0 + per; r++) {
        float c = s.coeff[r];
        const float4* row = (const float4*)(feat + (size_t)(src_base + r) * F);
        float4 v = __ldg(&row[lane]);
        part.x += c * v.x; part.y += c * v.y;
        part.z += c * v.z; part.w += c * v.w;
    }
    ((float4*)(s.partial + warp * F))[lane] = part;
    __syncthreads();

    if (tid < F) {
        float sum = 0.f;
        #pragma unroll
        for (int w = 0; w < 8; w++) sum += s.partial[w * F + tid];
        pooled[tid] = sum;
    }
    __syncthreads(); // smem reused by next relation
}

// Fused kernel: blocks [0,257) do weff/beff precompute; blocks [257, 257+1024)
// do the per-(layer,graph) aggregation. Independent work, one launch.
__global__ __launch_bounds__(256) void fused_kernel(
    const float* __restrict__ feat_lig, const float* __restrict__ feat_prot,
    const int* __restrict__ src_pl, const int* __restrict__ dst_pl,
    const int* __restrict__ src_ll, const int* __restrict__ dst_ll,
    const float* __restrict__ W_pl, const float* __restrict__ W_ll,
    const float* __restrict__ b_pl, const float* __restrict__ b_ll,
    const float* __restrict__ W_fc, const float* __restrict__ b_fc)
{
    const int tid  = threadIdx.x;

    if (blockIdx.x < 256) {
        // ---- weff rows: one warp per (rel,l,f) row, warp-reduced dot over h ----
        const int warp = tid >> 5, lane = tid & 31;
        const int bid  = blockIdx.x;
        const int rel  = bid >> 7;           // 0: pl, 1: ll
        const int l    = (bid >> 4) & 7;
        const int f    = ((bid & 15) << 3) + warp;

        const float* W    = rel ? W_ll : W_pl;
        float*       Weff = rel ? g_weff_ll : g_weff_pl;

        const float* wrow = W + ((size_t)l * F + f) * H;
        const float* fc   = W_fc + (size_t)l * H * OUT;

        float a0 = 0.f, a1 = 0.f;
        #pragma unroll
        for (int h = lane; h < H; h += 32) {
            float w = wrow[h];
            a0 += w * fc[h * OUT + 0];
            a1 += w * fc[h * OUT + 1];
        }
        #pragma unroll
        for (int o = 16; o > 0; o >>= 1) {
            a0 += __shfl_xor_sync(0xffffffffu, a0, o);
            a1 += __shfl_xor_sync(0xffffffffu, a1, o);
        }
        if (lane == 0) {
            Weff[((size_t)l * F + f) * OUT + 0] = a0;
            Weff[((size_t)l * F + f) * OUT + 1] = a1;
        }
        return;
    }
    if (blockIdx.x == 256) {
        // ---- beff = b_fc + sum_j (b_pl+b_ll)[j] * W_fc[j,:] ----
        __shared__ float red0[256], red1[256];
        float a0 = 0.f, a1 = 0.f;
        for (int j = tid; j < L * H; j += 256) {
            float bb = b_pl[j] + b_ll[j];
            a0 += bb * W_fc[j * OUT + 0];
            a1 += bb * W_fc[j * OUT + 1];
        }
        red0[tid] = a0; red1[tid] = a1;
        __syncthreads();
        #pragma unroll
        for (int st = 128; st > 0; st >>= 1) {
            if (tid < st) { red0[tid] += red0[tid + st]; red1[tid] += red1[tid + st]; }
            __syncthreads();
        }
        if (tid == 0) {
            g_beff[0] = red0[0] + b_fc[0];
            g_beff[1] = red1[0] + b_fc[1];
        }
        return;
    }

    // ---- aggregation blocks ----
    __shared__ SmemAgg s;
    const int gb = blockIdx.x - WEFF_BLOCKS;
    const int l = gb / B;
    const int b = gb % B;

    const float* fp = feat_prot + (size_t)l * N_PROT * F;
    const float* fl = feat_lig  + (size_t)l * N_LIG  * F;

    const size_t pl_off = (size_t)l * B * E_PL_G + (size_t)b * E_PL_G;
    const size_t ll_off = (size_t)l * B * E_LL_G + (size_t)b * E_LL_G;

    relation_pool(fp, src_pl + pl_off, dst_pl + pl_off,
                  E_PL_G, NP, b * NP, b * NL,
                  g_pooled_pl + ((size_t)l * B + b) * F, s);

    relation_pool(fl, src_ll + ll_off, dst_ll + ll_off,
                  E_LL_G, NL, b * NL, b * NL,
                  g_pooled_ll + ((size_t)l * B + b) * F, s);
}

__global__ __launch_bounds__(128) void final_kernel(float* __restrict__ out)
{
    const int b = blockIdx.x;
    const int f = threadIdx.x;  // 0..127

    float a0 = 0.f, a1 = 0.f;
    #pragma unroll
    for (int l = 0; l < L; l++) {
        float pp = g_pooled_pl[((size_t)l * B + b) * F + f];
        float pl = g_pooled_ll[((size_t)l * B + b) * F + f];
        const int wi = (l * F + f) * OUT;
        a0 += pp * g_weff_pl[wi + 0] + pl * g_weff_ll[wi + 0];
        a1 += pp * g_weff_pl[wi + 1] + pl * g_weff_ll[wi + 1];
    }

    __shared__ float red[2][128];
    red[0][f] = a0; red[1][f] = a1;
    __syncthreads();
    #pragma unroll
    for (int st = 64; st > 0; st >>= 1) {
        if (f < st) { red[0][f] += red[0][f + st]; red[1][f] += red[1][f + st]; }
        __syncthreads();
    }
    if (f < OUT) {
        float v = red[f][0] + g_beff[f];
        out[b * OUT + f] = 1.0f / (1.0f + expf(-v));
    }
}

extern "C" void kernel_launch(void* const* d_in, const int* in_sizes, int n_in,
                              void* d_out, int out_size)
{
    const float* feat_lig  = (const float*)d_in[0];
    const float* feat_prot = (const float*)d_in[1];
    const int*   src_pl    = (const int*)  d_in[2];
    const int*   dst_pl    = (const int*)  d_in[3];
    const int*   src_ll    = (const int*)  d_in[4];
    const int*   dst_ll    = (const int*)  d_in[5];
    const float* W_pl      = (const float*)d_in[6];
    const float* b_pl      = (const float*)d_in[7];
    const float* W_ll      = (const float*)d_in[8];
    const float* b_ll      = (const float*)d_in[9];
    const float* W_fc      = (const float*)d_in[10];
    const float* b_fc      = (const float*)d_in[11];
    float* out = (float*)d_out;

    fused_kernel<<<WEFF_BLOCKS + AGG_BLOCKS, 256>>>(
        feat_lig, feat_prot, src_pl, dst_pl, src_ll, dst_ll,
        W_pl, W_ll, b_pl, b_ll, W_fc, b_fc);
    final_kernel<<<B, 128>>>(out);
}

// round 5
// speedup vs baseline: 5.4708x; 1.0226x over previous
#include <cuda_runtime.h>

#define L 8
#define B 128
#define NL 32
#define NP 256
#define N_LIG (B*NL)
#define N_PROT (B*NP)
#define E_PL_G 1024
#define E_LL_G 256
#define F 128
#define H 256
#define OUT 2

#define WEFF_BLOCKS 257   // 256 weff-row blocks + 1 beff block
#define AGG_BLOCKS  (L*B)

// Scratch (device globals; no allocation allowed in kernel_launch)
__device__ float g_pooled_pl[L * B * F];
__device__ float g_pooled_ll[L * B * F];
__device__ float g_weff_pl[L * F * OUT];   // W_pl[l] @ W_fc[l*H:(l+1)*H]
__device__ float g_weff_ll[L * F * OUT];
__device__ float g_beff[OUT];

struct SmemAgg {
    alignas(16) float partial[8 * F];   // per-warp pooled partials
    unsigned short pack[E_PL_G];        // (dst_local<<8) | src_local
    int   cnt_src[NP];
    float coeff[NP];
    int   cnt_dst[NL];
    float rs_dst[NL];
};

// pooled[f] = sum_s coeff[s] * feat[src_base+s][f],
// coeff[s]  = rs_src[s] * (1/NL) * sum_{e: src=s} rs_dst[dst_e]
__device__ __forceinline__ void relation_pool(
    const float* __restrict__ feat,
    const int* __restrict__ src, const int* __restrict__ dst,
    int n_edges, int n_src, int src_base, int dst_base,
    float* __restrict__ pooled, SmemAgg& s)
{
    const int tid = threadIdx.x;

    // zero counters
    for (int i = tid; i < n_src; i += 256) s.cnt_src[i] = 0;
    if (tid < NL) s.cnt_dst[tid] = 0;
    __syncthreads();

    // load edges, localize, count degrees
    for (int e = tid; e < n_edges; e += 256) {
        int sl = src[e] - src_base;
        int dl = dst[e] - dst_base;
        s.pack[e] = (unsigned short)((dl << 8) | sl);
        atomicAdd(&s.cnt_src[sl], 1);
        atomicAdd(&s.cnt_dst[dl], 1);
    }
    __syncthreads();

    if (tid < NL) {
        int c = s.cnt_dst[tid];
        s.rs_dst[tid] = rsqrtf((float)(c > 0 ? c : 1));
    }
    for (int i = tid; i < n_src; i += 256) s.coeff[i] = 0.f;
    __syncthreads();

    // accumulate per-src coefficient
    for (int e = tid; e < n_edges; e += 256) {
        unsigned short p = s.pack[e];
        atomicAdd(&s.coeff[p & 255], s.rs_dst[p >> 8]);
    }
    __syncthreads();

    // fold rs_src and the 1/NL graph-mean
    for (int i = tid; i < n_src; i += 256) {
        int c = s.cnt_src[i];
        s.coeff[i] *= rsqrtf((float)(c > 0 ? c : 1)) * (1.0f / (float)NL);
    }
    __syncthreads();

    // dense, streaming weighted row-sum: warp w owns rows [w*per, (w+1)*per);
    // lane covers floats [4*lane, 4*lane+4); unrolled x8 for load batching (MLP)
    const int warp = tid >> 5, lane = tid & 31;
    const int per = n_src >> 3;
    const int r0 = warp * per;
    float4 part = make_float4(0.f, 0.f, 0.f, 0.f);
    #pragma unroll 8
    for (int r = r0; r < r0 + per; r++) {
        float c = s.coeff[r];
        const float4* row = (const float4*)(feat + (size_t)(src_base + r) * F);
        float4 v = __ldg(&row[lane]);
        part.x += c * v.x; part.y += c * v.y;
        part.z += c * v.z; part.w += c * v.w;
    }
    ((float4*)(s.partial + warp * F))[lane] = part;
    __syncthreads();

    if (tid < F) {
        float sum = 0.f;
        #pragma unroll
        for (int w = 0; w < 8; w++) sum += s.partial[w * F + tid];
        pooled[tid] = sum;
    }
    __syncthreads(); // smem reused by next relation
}

// Fused kernel: blocks [0,257) do weff/beff precompute; blocks [257, 257+1024)
// do the per-(layer,graph) aggregation. Independent work, one launch.
__global__ __launch_bounds__(256) void fused_kernel(
    const float* __restrict__ feat_lig, const float* __restrict__ feat_prot,
    const int* __restrict__ src_pl, const int* __restrict__ dst_pl,
    const int* __restrict__ src_ll, const int* __restrict__ dst_ll,
    const float* __restrict__ W_pl, const float* __restrict__ W_ll,
    const float* __restrict__ b_pl, const float* __restrict__ b_ll,
    const float* __restrict__ W_fc, const float* __restrict__ b_fc)
{
    const int tid  = threadIdx.x;

    if (blockIdx.x < 256) {
        // ---- weff rows: one warp per (rel,l,f) row, warp-reduced dot over h ----
        const int warp = tid >> 5, lane = tid & 31;
        const int bid  = blockIdx.x;
        const int rel  = bid >> 7;           // 0: pl, 1: ll
        const int l    = (bid >> 4) & 7;
        const int f    = ((bid & 15) << 3) + warp;

        const float* W    = rel ? W_ll : W_pl;
        float*       Weff = rel ? g_weff_ll : g_weff_pl;

        const float* wrow = W + ((size_t)l * F + f) * H;
        const float* fc   = W_fc + (size_t)l * H * OUT;

        float a0 = 0.f, a1 = 0.f;
        #pragma unroll
        for (int h = lane; h < H; h += 32) {
            float w = wrow[h];
            a0 += w * fc[h * OUT + 0];
            a1 += w * fc[h * OUT + 1];
        }
        #pragma unroll
        for (int o = 16; o > 0; o >>= 1) {
            a0 += __shfl_xor_sync(0xffffffffu, a0, o);
            a1 += __shfl_xor_sync(0xffffffffu, a1, o);
        }
        if (lane == 0) {
            Weff[((size_t)l * F + f) * OUT + 0] = a0;
            Weff[((size_t)l * F + f) * OUT + 1] = a1;
        }
        return;
    }
    if (blockIdx.x == 256) {
        // ---- beff = b_fc + sum_j (b_pl+b_ll)[j] * W_fc[j,:] ----
        __shared__ float red0[256], red1[256];
        float a0 = 0.f, a1 = 0.f;
        for (int j = tid; j < L * H; j += 256) {
            float bb = b_pl[j] + b_ll[j];
            a0 += bb * W_fc[j * OUT + 0];
            a1 += bb * W_fc[j * OUT + 1];
        }
        red0[tid] = a0; red1[tid] = a1;
        __syncthreads();
        #pragma unroll
        for (int st = 128; st > 0; st >>= 1) {
            if (tid < st) { red0[tid] += red0[tid + st]; red1[tid] += red1[tid + st]; }
            __syncthreads();
        }
        if (tid == 0) {
            g_beff[0] = red0[0] + b_fc[0];
            g_beff[1] = red1[0] + b_fc[1];
        }
        return;
    }

    // ---- aggregation blocks ----
    __shared__ SmemAgg s;
    const int gb = blockIdx.x - WEFF_BLOCKS;
    const int l = gb / B;
    const int b = gb % B;

    const float* fp = feat_prot + (size_t)l * N_PROT * F;
    const float* fl = feat_lig  + (size_t)l * N_LIG  * F;

    const size_t pl_off = (size_t)l * B * E_PL_G + (size_t)b * E_PL_G;
    const size_t ll_off = (size_t)l * B * E_LL_G + (size_t)b * E_LL_G;

    relation_pool(fp, src_pl + pl_off, dst_pl + pl_off,
                  E_PL_G, NP, b * NP, b * NL,
                  g_pooled_pl + ((size_t)l * B + b) * F, s);

    relation_pool(fl, src_ll + ll_off, dst_ll + ll_off,
                  E_LL_G, NL, b * NL, b * NL,
                  g_pooled_ll + ((size_t)l * B + b) * F, s);
}

// One block per graph b; warp w owns layer w. All-vector loads, warp reduction.
__global__ __launch_bounds__(256) void final_kernel(float* __restrict__ out)
{
    const int b    = blockIdx.x;
    const int warp = threadIdx.x >> 5;   // layer
    const int lane = threadIdx.x & 31;   // 4 features per lane

    const float4* pp = (const float4*)(g_pooled_pl + ((size_t)warp * B + b) * F);
    const float4* pl = (const float4*)(g_pooled_ll + ((size_t)warp * B + b) * F);
    const float4* wp = (const float4*)(g_weff_pl + (size_t)warp * F * OUT);
    const float4* wl = (const float4*)(g_weff_ll + (size_t)warp * F * OUT);

    float4 vp  = __ldg(&pp[lane]);
    float4 vl  = __ldg(&pl[lane]);
    float4 wp0 = __ldg(&wp[lane * 2]);      // (f0:o0,o1, f1:o0,o1)
    float4 wp1 = __ldg(&wp[lane * 2 + 1]);  // (f2:o0,o1, f3:o0,o1)
    float4 wl0 = __ldg(&wl[lane * 2]);
    float4 wl1 = __ldg(&wl[lane * 2 + 1]);

    float a0 = vp.x * wp0.x + vp.y * wp0.z + vp.z * wp1.x + vp.w * wp1.z
             + vl.x * wl0.x + vl.y * wl0.z + vl.z * wl1.x + vl.w * wl1.z;
    float a1 = vp.x * wp0.y + vp.y * wp0.w + vp.z * wp1.y + vp.w * wp1.w
             + vl.x * wl0.y + vl.y * wl0.w + vl.z * wl1.y + vl.w * wl1.w;

    #pragma unroll
    for (int o = 16; o > 0; o >>= 1) {
        a0 += __shfl_xor_sync(0xffffffffu, a0, o);
        a1 += __shfl_xor_sync(0xffffffffu, a1, o);
    }

    __shared__ float s0[8], s1[8];
    if (lane == 0) { s0[warp] = a0; s1[warp] = a1; }
    __syncthreads();
    if (threadIdx.x == 0) {
        float t0 = 0.f, t1 = 0.f;
        #pragma unroll
        for (int w = 0; w < 8; w++) { t0 += s0[w]; t1 += s1[w]; }
        out[b * OUT + 0] = 1.0f / (1.0f + expf(-(t0 + g_beff[0])));
        out[b * OUT + 1] = 1.0f / (1.0f + expf(-(t1 + g_beff[1])));
    }
}

extern "C" void kernel_launch(void* const* d_in, const int* in_sizes, int n_in,
                              void* d_out, int out_size)
{
    const float* feat_lig  = (const float*)d_in[0];
    const float* feat_prot = (const float*)d_in[1];
    const int*   src_pl    = (const int*)  d_in[2];
    const int*   dst_pl    = (const int*)  d_in[3];
    const int*   src_ll    = (const int*)  d_in[4];
    const int*   dst_ll    = (const int*)  d_in[5];
    const float* W_pl      = (const float*)d_in[6];
    const float* b_pl      = (const float*)d_in[7];
    const float* W_ll      = (const float*)d_in[8];
    const float* b_ll      = (const float*)d_in[9];
    const float* W_fc      = (const float*)d_in[10];
    const float* b_fc      = (const float*)d_in[11];
    float* out = (float*)d_out;

    fused_kernel<<<WEFF_BLOCKS + AGG_BLOCKS, 256>>>(
        feat_lig, feat_prot, src_pl, dst_pl, src_ll, dst_ll,
        W_pl, W_ll, b_pl, b_ll, W_fc, b_fc);
    final_kernel<<<B, 256>>>(out);
}

// round 6
// speedup vs baseline: 5.6990x; 1.0417x over previous
#include <cuda_runtime.h>

#define L 8
#define B 128
#define NL 32
#define NP 256
#define N_LIG (B*NL)
#define N_PROT (B*NP)
#define E_PL_G 1024
#define E_LL_G 256
#define F 128
#define H 256
#define OUT 2

#define WEFF_BLOCKS 257   // 256 weff-row blocks + 1 beff block
#define AGG_BLOCKS  (L*B)
#define WEFF_TARGET 257

// Scratch (device globals, zero-initialized; protocol restores zeros each call)
__device__ float g_weff_pl[L * F * OUT];   // W_pl[l] @ W_fc[l*H:(l+1)*H]
__device__ float g_weff_ll[L * F * OUT];
__device__ float g_beff[OUT];
__device__ int   g_weff_ready;             // counts finished weff/beff blocks
__device__ float g_logit[B * OUT];         // accumulated logits per graph
__device__ int   g_cnt[B];                 // finished agg blocks per graph
__device__ int   g_done;                   // finished graphs

struct SmemAgg {
    alignas(16) float partial[8 * F];   // per-warp pooled partials
    alignas(16) float pool0[F];         // pooled PL (stays in smem)
    alignas(16) float pool1[F];         // pooled LL
    unsigned short pack[E_PL_G];        // (dst_local<<8) | src_local
    int   cnt_src[NP];
    float coeff[NP];
    int   cnt_dst[NL];
    float rs_dst[NL];
};

// pooled[f] = sum_s coeff[s] * feat[src_base+s][f],
// coeff[s]  = rs_src[s] * (1/NL) * sum_{e: src=s} rs_dst[dst_e]
__device__ __forceinline__ void relation_pool(
    const float* __restrict__ feat,
    const int* __restrict__ src, const int* __restrict__ dst,
    int n_edges, int n_src, int src_base, int dst_base,
    float* __restrict__ pooled, SmemAgg& s)
{
    const int tid = threadIdx.x;

    // zero counters
    for (int i = tid; i < n_src; i += 256) s.cnt_src[i] = 0;
    if (tid < NL) s.cnt_dst[tid] = 0;
    __syncthreads();

    // load edges, localize, count degrees
    for (int e = tid; e < n_edges; e += 256) {
        int sl = src[e] - src_base;
        int dl = dst[e] - dst_base;
        s.pack[e] = (unsigned short)((dl << 8) | sl);
        atomicAdd(&s.cnt_src[sl], 1);
        atomicAdd(&s.cnt_dst[dl], 1);
    }
    __syncthreads();

    if (tid < NL) {
        int c = s.cnt_dst[tid];
        s.rs_dst[tid] = rsqrtf((float)(c > 0 ? c : 1));
    }
    for (int i = tid; i < n_src; i += 256) s.coeff[i] = 0.f;
    __syncthreads();

    // accumulate per-src coefficient
    for (int e = tid; e < n_edges; e += 256) {
        unsigned short p = s.pack[e];
        atomicAdd(&s.coeff[p & 255], s.rs_dst[p >> 8]);
    }
    __syncthreads();

    // fold rs_src and the 1/NL graph-mean
    for (int i = tid; i < n_src; i += 256) {
        int c = s.cnt_src[i];
        s.coeff[i] *= rsqrtf((float)(c > 0 ? c : 1)) * (1.0f / (float)NL);
    }
    __syncthreads();

    // dense, streaming weighted row-sum: warp w owns rows [w*per, (w+1)*per);
    // lane covers floats [4*lane, 4*lane+4); unrolled x8 for load batching (MLP)
    const int warp = tid >> 5, lane = tid & 31;
    const int per = n_src >> 3;
    const int r0 = warp * per;
    float4 part = make_float4(0.f, 0.f, 0.f, 0.f);
    #pragma unroll 8
    for (int r = r0; r < r0 + per; r++) {
        float c = s.coeff[r];
        const float4* row = (const float4*)(feat + (size_t)(src_base + r) * F);
        float4 v = __ldg(&row[lane]);
        part.x += c * v.x; part.y += c * v.y;
        part.z += c * v.z; part.w += c * v.w;
    }
    ((float4*)(s.partial + warp * F))[lane] = part;
    __syncthreads();

    if (tid < F) {
        float sum = 0.f;
        #pragma unroll
        for (int w = 0; w < 8; w++) sum += s.partial[w * F + tid];
        pooled[tid] = sum;
    }
    __syncthreads(); // smem reused by next relation
}

// Single kernel. Blocks [0,257): weff/beff precompute (signal via g_weff_ready).
// Blocks [257, 257+1024): per-(layer,graph) aggregation + logit contribution;
// last-arriving block per graph applies beff + sigmoid and writes out.
__global__ __launch_bounds__(256) void fused_kernel(
    const float* __restrict__ feat_lig, const float* __restrict__ feat_prot,
    const int* __restrict__ src_pl, const int* __restrict__ dst_pl,
    const int* __restrict__ src_ll, const int* __restrict__ dst_ll,
    const float* __restrict__ W_pl, const float* __restrict__ W_ll,
    const float* __restrict__ b_pl, const float* __restrict__ b_ll,
    const float* __restrict__ W_fc, const float* __restrict__ b_fc,
    float* __restrict__ out)
{
    const int tid  = threadIdx.x;
    const int warp = tid >> 5, lane = tid & 31;

    if (blockIdx.x < 256) {
        // ---- weff rows: one warp per (rel,l,f) row, warp-reduced dot over h ----
        const int bid  = blockIdx.x;
        const int rel  = bid >> 7;           // 0: pl, 1: ll
        const int l    = (bid >> 4) & 7;
        const int f    = ((bid & 15) << 3) + warp;

        const float* W    = rel ? W_ll : W_pl;
        float*       Weff = rel ? g_weff_ll : g_weff_pl;

        const float* wrow = W + ((size_t)l * F + f) * H;
        const float* fc   = W_fc + (size_t)l * H * OUT;

        float a0 = 0.f, a1 = 0.f;
        #pragma unroll
        for (int h = lane; h < H; h += 32) {
            float w = wrow[h];
            a0 += w * fc[h * OUT + 0];
            a1 += w * fc[h * OUT + 1];
        }
        #pragma unroll
        for (int o = 16; o > 0; o >>= 1) {
            a0 += __shfl_xor_sync(0xffffffffu, a0, o);
            a1 += __shfl_xor_sync(0xffffffffu, a1, o);
        }
        if (lane == 0) {
            Weff[((size_t)l * F + f) * OUT + 0] = a0;
            Weff[((size_t)l * F + f) * OUT + 1] = a1;
        }
        __syncthreads();
        if (tid == 0) {
            __threadfence();
            atomicAdd(&g_weff_ready, 1);
        }
        return;
    }
    if (blockIdx.x == 256) {
        // ---- beff = b_fc + sum_j (b_pl+b_ll)[j] * W_fc[j,:] ----
        __shared__ float red0[256], red1[256];
        float a0 = 0.f, a1 = 0.f;
        for (int j = tid; j < L * H; j += 256) {
            float bb = b_pl[j] + b_ll[j];
            a0 += bb * W_fc[j * OUT + 0];
            a1 += bb * W_fc[j * OUT + 1];
        }
        red0[tid] = a0; red1[tid] = a1;
        __syncthreads();
        #pragma unroll
        for (int st = 128; st > 0; st >>= 1) {
            if (tid < st) { red0[tid] += red0[tid + st]; red1[tid] += red1[tid + st]; }
            __syncthreads();
        }
        if (tid == 0) {
            g_beff[0] = red0[0] + b_fc[0];
            g_beff[1] = red1[0] + b_fc[1];
            __threadfence();
            atomicAdd(&g_weff_ready, 1);
        }
        return;
    }

    // ---- aggregation blocks ----
    __shared__ SmemAgg s;
    const int gb = blockIdx.x - WEFF_BLOCKS;
    const int l = gb / B;
    const int b = gb % B;

    const float* fp = feat_prot + (size_t)l * N_PROT * F;
    const float* fl = feat_lig  + (size_t)l * N_LIG  * F;

    const size_t pl_off = (size_t)l * B * E_PL_G + (size_t)b * E_PL_G;
    const size_t ll_off = (size_t)l * B * E_LL_G + (size_t)b * E_LL_G;

    relation_pool(fp, src_pl + pl_off, dst_pl + pl_off,
                  E_PL_G, NP, b * NP, b * NL, s.pool0, s);

    relation_pool(fl, src_ll + ll_off, dst_ll + ll_off,
                  E_LL_G, NL, b * NL, b * NL, s.pool1, s);

    // wait for weff/beff (weff blocks are bids 0..256 -> wave 1; done long ago)
    if (tid == 0) {
        while (atomicCAS(&g_weff_ready, WEFF_TARGET, WEFF_TARGET) != WEFF_TARGET) {}
    }
    __syncthreads();

    // logit contribution of this (l, b): dot(pool, weff[l]) over 128 features
    float a0 = 0.f, a1 = 0.f;
    if (tid < F) {
        float pp = s.pool0[tid];
        float pl = s.pool1[tid];
        const int wi = (l * F + tid) * OUT;
        a0 = pp * g_weff_pl[wi + 0] + pl * g_weff_ll[wi + 0];
        a1 = pp * g_weff_pl[wi + 1] + pl * g_weff_ll[wi + 1];
    }
    #pragma unroll
    for (int o = 16; o > 0; o >>= 1) {
        a0 += __shfl_xor_sync(0xffffffffu, a0, o);
        a1 += __shfl_xor_sync(0xffffffffu, a1, o);
    }
    __shared__ float s0[8], s1[8];
    if (lane == 0) { s0[warp] = a0; s1[warp] = a1; }
    __syncthreads();

    if (tid == 0) {
        float t0 = s0[0] + s0[1] + s0[2] + s0[3];  // warps 4..7 had tid>=128 -> 0
        float t1 = s1[0] + s1[1] + s1[2] + s1[3];
        atomicAdd(&g_logit[b * OUT + 0], t0);
        atomicAdd(&g_logit[b * OUT + 1], t1);
        __threadfence();
        int old = atomicAdd(&g_cnt[b], 1);
        if (old == L - 1) {
            // all 8 layer contributions are in (their adds fenced before count)
            float v0 = atomicAdd(&g_logit[b * OUT + 0], 0.f) + g_beff[0];
            float v1 = atomicAdd(&g_logit[b * OUT + 1], 0.f) + g_beff[1];
            out[b * OUT + 0] = 1.0f / (1.0f + expf(-v0));
            out[b * OUT + 1] = 1.0f / (1.0f + expf(-v1));
            // restore zeros for the next replay
            g_logit[b * OUT + 0] = 0.f;
            g_logit[b * OUT + 1] = 0.f;
            g_cnt[b] = 0;
            __threadfence();
            int d = atomicAdd(&g_done, 1);
            if (d == B - 1) { g_done = 0; g_weff_ready = 0; __threadfence(); }
        }
    }
}

extern "C" void kernel_launch(void* const* d_in, const int* in_sizes, int n_in,
                              void* d_out, int out_size)
{
    const float* feat_lig  = (const float*)d_in[0];
    const float* feat_prot = (const float*)d_in[1];
    const int*   src_pl    = (const int*)  d_in[2];
    const int*   dst_pl    = (const int*)  d_in[3];
    const int*   src_ll    = (const int*)  d_in[4];
    const int*   dst_ll    = (const int*)  d_in[5];
    const float* W_pl      = (const float*)d_in[6];
    const float* b_pl      = (const float*)d_in[7];
    const float* W_ll      = (const float*)d_in[8];
    const float* b_ll      = (const float*)d_in[9];
    const float* W_fc      = (const float*)d_in[10];
    const float* b_fc      = (const float*)d_in[11];
    float* out = (float*)d_out;

    fused_kernel<<<WEFF_BLOCKS + AGG_BLOCKS, 256>>>(
        feat_lig, feat_prot, src_pl, dst_pl, src_ll, dst_ll,
        W_pl, W_ll, b_pl, b_ll, W_fc, b_fc, out);
}